// round 15
// baseline (speedup 1.0000x reference)
#include <cuda_runtime.h>
#include <cuda_bf16.h>
#include <cstdint>

// ---------------- scratch ----------------
__device__ float g_G[8 * 64 * 64];     // reduced Gram (zeroed per call, RED.F32 target)
__device__ float g_m1[8 * 64];         // token sums   (zeroed per call, RED.F32 target)

__device__ __forceinline__ uint32_t smem_u32(const void* p) {
    uint32_t a;
    asm("{ .reg .u64 t; cvta.to.shared.u64 t, %1; cvt.u32.u64 %0, t; }" : "=r"(a) : "l"(p));
    return a;
}
__device__ __forceinline__ void ldsm4(uint32_t& r0, uint32_t& r1, uint32_t& r2, uint32_t& r3,
                                      uint32_t addr) {
    asm volatile("ldmatrix.sync.aligned.m8n8.x4.shared.b16 {%0,%1,%2,%3}, [%4];"
                 : "=r"(r0), "=r"(r1), "=r"(r2), "=r"(r3) : "r"(addr));
}
__device__ __forceinline__ void ldsm4t(uint32_t& r0, uint32_t& r1, uint32_t& r2, uint32_t& r3,
                                       uint32_t addr) {
    asm volatile("ldmatrix.sync.aligned.m8n8.x4.trans.shared.b16 {%0,%1,%2,%3}, [%4];"
                 : "=r"(r0), "=r"(r1), "=r"(r2), "=r"(r3) : "r"(addr));
}
__device__ __forceinline__ void mma_bf16(float c[4], uint32_t a0, uint32_t a1, uint32_t a2,
                                         uint32_t a3, uint32_t b0, uint32_t b1) {
    asm volatile(
        "mma.sync.aligned.m16n8k16.row.col.f32.bf16.bf16.f32 "
        "{%0,%1,%2,%3}, {%4,%5,%6,%7}, {%8,%9}, {%0,%1,%2,%3};"
        : "+f"(c[0]), "+f"(c[1]), "+f"(c[2]), "+f"(c[3])
        : "r"(a0), "r"(a1), "r"(a2), "r"(a3), "r"(b0), "r"(b1));
}

// ---------------- K1: Gram via HMMA, RED.F32 epilogue ----------------
// grid 512 (b*64 + y), 256 threads (8 warps). T[token 64][hi|lo] bf16, stride 136.
// G = T.T^T + T.Tswap^T (exact); fragments reduced into g_G via atomicAdd (RED).
#define GTS 136
__global__ __launch_bounds__(256) void gram_kernel(const float* __restrict__ x) {
    __shared__ __align__(16) __nv_bfloat16 T[64 * GTS];
    __shared__ float m1w[8][64];

    int b = blockIdx.x >> 6, y = blockIdx.x & 63;
    int tid = threadIdx.x, w = tid >> 5, l = tid & 31;
    uint32_t t_b = smem_u32(T);

    m1w[w][l] = 0.f; m1w[w][l + 32] = 0.f;

    const float* xb = x + b * 262144;
    #pragma unroll
    for (int it = 0; it < 4; ++it) {
        int f4 = it * 256 + tid;            // 0..1023
        int j = f4 >> 4, x4 = f4 & 15;
        float4 v = *(const float4*)(xb + ((j >> 3) * 64 + y) * 512 + (j & 7) * 64 + x4 * 4);
        __nv_bfloat162 h01 = __float22bfloat162_rn(make_float2(v.x, v.y));
        __nv_bfloat162 h23 = __float22bfloat162_rn(make_float2(v.z, v.w));
        float2 f01 = __bfloat1622float2(h01);
        float2 f23 = __bfloat1622float2(h23);
        __nv_bfloat162 l01 = __float22bfloat162_rn(make_float2(v.x - f01.x, v.y - f01.y));
        __nv_bfloat162 l23 = __float22bfloat162_rn(make_float2(v.z - f23.x, v.w - f23.y));
        *(uint2*)&T[j * GTS + x4 * 4]      = make_uint2(*(uint32_t*)&h01, *(uint32_t*)&h23);
        *(uint2*)&T[j * GTS + 64 + x4 * 4] = make_uint2(*(uint32_t*)&l01, *(uint32_t*)&l23);
        float s4 = (v.x + v.y) + (v.z + v.w);
        s4 += __shfl_xor_sync(0xffffffffu, s4, 1);
        s4 += __shfl_xor_sync(0xffffffffu, s4, 2);
        s4 += __shfl_xor_sync(0xffffffffu, s4, 4);
        s4 += __shfl_xor_sync(0xffffffffu, s4, 8);
        if ((l & 15) == 0) m1w[w][j] += s4;
    }
    __syncthreads();

    if (tid < 64) {
        float s = 0.f;
        #pragma unroll
        for (int ww = 0; ww < 8; ++ww) s += m1w[ww][tid];
        atomicAdd(&g_m1[b * 64 + tid], s);    // RED.F32 (no return use)
    }

    int rw = w & 3, nh = w >> 2;
    int r0 = 16 * rw, n0 = 32 * nh;
    float c[4][4];
    #pragma unroll
    for (int q = 0; q < 4; ++q)
        #pragma unroll
        for (int e = 0; e < 4; ++e) c[q][e] = 0.f;

    int arow = r0 + (l & 15), ak = (l >> 4) << 3;
    int brow = ((l >> 4) << 3) + (l & 7), bk = ((l >> 3) & 1) << 3;

    #pragma unroll
    for (int kk = 0; kk < 128; kk += 16) {
        uint32_t a0, a1, a2, a3;
        ldsm4(a0, a1, a2, a3, t_b + (arow * GTS + kk + ak) * 2);
        int kc = kk ^ 64;                   // swapped-half k for cross terms
        #pragma unroll
        for (int t = 0; t < 2; ++t) {
            int row = n0 + 16 * t + brow;
            uint32_t b0, b1, b2, b3;
            ldsm4(b0, b1, b2, b3, t_b + (row * GTS + kk + bk) * 2);
            mma_bf16(c[2 * t],     a0, a1, a2, a3, b0, b1);
            mma_bf16(c[2 * t + 1], a0, a1, a2, a3, b2, b3);
            ldsm4(b0, b1, b2, b3, t_b + (row * GTS + kc + bk) * 2);
            mma_bf16(c[2 * t],     a0, a1, a2, a3, b0, b1);
            mma_bf16(c[2 * t + 1], a0, a1, a2, a3, b2, b3);
        }
    }

    // RED.F32 directly into reduced G (split-K over the 64 y-blocks of batch b)
    float* gp = &g_G[b * 4096];
    int er = r0 + (l >> 2), ec = 2 * (l & 3);
    #pragma unroll
    for (int q = 0; q < 4; ++q) {
        int col = n0 + 16 * (q >> 1) + 8 * (q & 1) + ec;
        atomicAdd(&gp[er * 64 + col],           c[q][0]);
        atomicAdd(&gp[er * 64 + col + 1],       c[q][1]);
        atomicAdd(&gp[(er + 8) * 64 + col],     c[q][2]);
        atomicAdd(&gp[(er + 8) * 64 + col + 1], c[q][3]);
    }
}

// ---------------- K2: softmax prologue + out = M @ X + const via HMMA ----------------
// grid 512 (b*64+y), 256 threads. Per-block redundant: weight collapse + softmax
// over reduced g_G -> Asm ([Mh|Ml] split bf16, stride 136). Bsm holds G(float)
// during softmax, then X tiles ([Xh;Xl], stride 72) for the mma.
#define ATS 136
#define BTS 72
__global__ __launch_bounds__(256) void out_kernel(const float* __restrict__ x,
                                                  float* __restrict__ out,
        const float* __restrict__ w1, const float* __restrict__ b1,
        const float* __restrict__ wqkv, const float* __restrict__ wproj,
        const float* __restrict__ bproj, const float* __restrict__ w2,
        const float* __restrict__ b2) {
    __shared__ __align__(16) __nv_bfloat16 Asm[64 * ATS];
    __shared__ __align__(16) __nv_bfloat16 Bsm[128 * BTS];   // >=16KB: doubles as Gs(float)
    __shared__ float Aw[96], B0w[96], tCw[32];
    __shared__ float sal[4], sbe[4], sga[4], sde[4], swh[4], scst[1];
    __shared__ float m1s[64];

    int b = blockIdx.x >> 6, y = blockIdx.x & 63;
    int tid = threadIdx.x, w = tid >> 5, l = tid & 31;
    uint32_t a_b = smem_u32(Asm), b_b = smem_u32(Bsm);
    float* Gs = (float*)Bsm;

    // ---- phase A: load reduced G + m1 + weight collapse stage 1 ----
    {
        const float4* gg = (const float4*)&g_G[b * 4096];
        #pragma unroll
        for (int it = 0; it < 4; ++it)
            ((float4*)Gs)[it * 256 + tid] = gg[it * 256 + tid];
    }
    if (tid < 64) m1s[tid] = g_m1[b * 64 + tid];
    if (tid < 96) {
        float a = 0.f, bb = 0.f;
        #pragma unroll
        for (int c = 0; c < 32; ++c) {
            float wv = wqkv[tid * 32 + c];
            a += wv * w1[c];
            bb += wv * b1[c];
        }
        Aw[tid] = a; B0w[tid] = bb;
    }
    if (tid >= 128 && tid < 160) {
        int c = tid - 128;
        float s = 0.f;
        #pragma unroll
        for (int o = 0; o < 32; ++o) s += w2[o] * wproj[o * 32 + c];
        tCw[c] = s;
    }
    __syncthreads();

    // ---- phase B: collapse stage 2 ----
    if (tid >= 128 && tid < 132) {
        int h = tid - 128;
        float al = 0.f, be = 0.f, ga = 0.f, de = 0.f, wh = 0.f;
        #pragma unroll
        for (int dd = 0; dd < 8; ++dd) {
            int c = h * 8 + dd;
            float aq = Aw[c], ak = Aw[32 + c], bq = B0w[c], bk = B0w[32 + c];
            al += aq * ak; be += aq * bk; ga += bq * ak; de += bq * bk;
            wh += tCw[c] * Aw[64 + c];
        }
        sal[h] = al; sbe[h] = be; sga[h] = ga; sde[h] = de; swh[h] = wh;
    }
    if (tid == 132) {
        float c = b2[0];
        #pragma unroll
        for (int o = 0; o < 32; ++o) c += w2[o] * bproj[o];
        #pragma unroll
        for (int cc = 0; cc < 32; ++cc) c += tCw[cc] * B0w[64 + cc];
        scst[0] = c;
    }
    __syncthreads();

    // ---- phase C: redundant softmax -> Asm (split bf16), warp w owns rows 8w.. ----
    {
        const float scale = 1.0f / (4096.0f * 2.8284271247461903f);
        #pragma unroll
        for (int r = 0; r < 8; ++r) {
            int i = w * 8 + r;
            float g0 = Gs[i * 64 + l], g1 = Gs[i * 64 + 32 + l];
            float m1i = m1s[i], m1l = m1s[l], m1l2 = m1s[l + 32];
            float acc0 = 0.f, acc1 = 0.f;
            #pragma unroll
            for (int h = 0; h < 4; ++h) {
                float al = sal[h] * scale, be = sbe[h] * scale;
                float ga = sga[h] * scale, de = sde[h] * scale * 4096.f;
                float whh = swh[h];
                float base = be * m1i + de;
                float s0 = al * g0 + ga * m1l  + base;
                float s1 = al * g1 + ga * m1l2 + base;
                float mx = fmaxf(s0, s1);
                #pragma unroll
                for (int off = 16; off > 0; off >>= 1)
                    mx = fmaxf(mx, __shfl_xor_sync(0xffffffffu, mx, off));
                float e0 = __expf(s0 - mx), e1 = __expf(s1 - mx);
                float sm = e0 + e1;
                #pragma unroll
                for (int off = 16; off > 0; off >>= 1)
                    sm += __shfl_xor_sync(0xffffffffu, sm, off);
                float f = whh / sm;
                acc0 += e0 * f; acc1 += e1 * f;
            }
            __nv_bfloat16 h0 = __float2bfloat16(acc0);
            __nv_bfloat16 h1 = __float2bfloat16(acc1);
            Asm[i * ATS + l]           = h0;
            Asm[i * ATS + 64 + l]      = __float2bfloat16(acc0 - __bfloat162float(h0));
            Asm[i * ATS + l + 32]      = h1;
            Asm[i * ATS + 64 + l + 32] = __float2bfloat16(acc1 - __bfloat162float(h1));
        }
    }
    __syncthreads();

    // ---- phase D: fill Bsm with X row y (overwrites Gs) ----
    const float* xb = x + b * 262144;
    #pragma unroll
    for (int it = 0; it < 4; ++it) {
        int f4 = it * 256 + tid;
        int j = f4 >> 4, x4 = f4 & 15;
        float4 v = *(const float4*)(xb + ((j >> 3) * 64 + y) * 512 + (j & 7) * 64 + x4 * 4);
        __nv_bfloat162 h01 = __float22bfloat162_rn(make_float2(v.x, v.y));
        __nv_bfloat162 h23 = __float22bfloat162_rn(make_float2(v.z, v.w));
        float2 f01 = __bfloat1622float2(h01);
        float2 f23 = __bfloat1622float2(h23);
        __nv_bfloat162 l01 = __float22bfloat162_rn(make_float2(v.x - f01.x, v.y - f01.y));
        __nv_bfloat162 l23 = __float22bfloat162_rn(make_float2(v.z - f23.x, v.w - f23.y));
        *(uint2*)&Bsm[j * BTS + x4 * 4]        = make_uint2(*(uint32_t*)&h01, *(uint32_t*)&h23);
        *(uint2*)&Bsm[(64 + j) * BTS + x4 * 4] = make_uint2(*(uint32_t*)&l01, *(uint32_t*)&l23);
    }
    __syncthreads();

    // ---- phase E: out mma (12 k16 iters: Mh*Xh, Ml*Xh, Mh*Xl) + store ----
    int rw = w & 3, nh = w >> 2;
    int r0 = 16 * rw;
    float c[4][4];
    #pragma unroll
    for (int t = 0; t < 4; ++t)
        #pragma unroll
        for (int q = 0; q < 4; ++q) c[t][q] = 0.f;

    int arow = r0 + (l & 15), ak = (l >> 4) << 3;
    int btrow = l & 15, btcol = (l >> 4) << 3;

    #pragma unroll
    for (int it = 0; it < 12; ++it) {
        int ka = (it < 4) ? it * 16 : (it < 8 ? 64 + (it - 4) * 16 : (it - 8) * 16);
        int kb = (it < 8) ? (it & 3) * 16 : 64 + (it - 8) * 16;
        uint32_t a0, a1, a2, a3;
        ldsm4(a0, a1, a2, a3, a_b + (arow * ATS + ka + ak) * 2);
        #pragma unroll
        for (int t = 0; t < 2; ++t) {
            int n0 = nh * 32 + 16 * t;
            uint32_t b0, b1, b2, b3;
            ldsm4t(b0, b1, b2, b3, b_b + ((kb + btrow) * BTS + n0 + btcol) * 2);
            mma_bf16(c[2 * t],     a0, a1, a2, a3, b0, b1);
            mma_bf16(c[2 * t + 1], a0, a1, a2, a3, b2, b3);
        }
    }

    float cst = scst[0];
    float* ob = out + b * 262144;
    int er = r0 + (l >> 2), ec = 2 * (l & 3);
    #pragma unroll
    for (int t = 0; t < 4; ++t) {
        int col = nh * 32 + 8 * t + ec;
        int s0 = er, s1 = er + 8;
        *(float2*)&ob[((s0 >> 3) * 64 + y) * 512 + (s0 & 7) * 64 + col] =
            make_float2(c[t][0] + cst, c[t][1] + cst);
        *(float2*)&ob[((s1 >> 3) * 64 + y) * 512 + (s1 & 7) * 64 + col] =
            make_float2(c[t][2] + cst, c[t][3] + cst);
    }
}

extern "C" void kernel_launch(void* const* d_in, const int* in_sizes, int n_in,
                              void* d_out, int out_size) {
    const float* x     = (const float*)d_in[0];
    const float* w1    = (const float*)d_in[3];
    const float* b1    = (const float*)d_in[4];
    const float* wqkv  = (const float*)d_in[5];
    const float* wproj = (const float*)d_in[6];
    const float* bproj = (const float*)d_in[7];
    const float* w2    = (const float*)d_in[8];
    const float* b2    = (const float*)d_in[9];
    float* out = (float*)d_out;

    void* gG = nullptr; void* gm1 = nullptr;
    cudaGetSymbolAddress(&gG, g_G);
    cudaGetSymbolAddress(&gm1, g_m1);
    cudaMemsetAsync(gG, 0, 8 * 64 * 64 * sizeof(float));
    cudaMemsetAsync(gm1, 0, 8 * 64 * sizeof(float));

    gram_kernel<<<512, 256>>>(x);
    out_kernel<<<512, 256>>>(x, out, w1, b1, wqkv, wproj, bproj, w2, b2);
}

// round 16
// speedup vs baseline: 1.9600x; 1.9600x over previous
#include <cuda_runtime.h>
#include <cuda_bf16.h>
#include <cuda_fp16.h>
#include <cstdint>

// ---------------- scratch ----------------
__device__ float g_Gpart[8 * 64 * 64 * 64];   // split-K gram partials (8 MB)
__device__ float g_m1part[8 * 64 * 64];       // token-sum partials
__device__ __half g_Mh[8 * 64 * 64];          // mixing matrix fp16 [b][s][j]
__device__ float g_cst[1];

__device__ __forceinline__ uint32_t smem_u32(const void* p) {
    uint32_t a;
    asm("{ .reg .u64 t; cvta.to.shared.u64 t, %1; cvt.u32.u64 %0, t; }" : "=r"(a) : "l"(p));
    return a;
}
__device__ __forceinline__ void ldsm4(uint32_t& r0, uint32_t& r1, uint32_t& r2, uint32_t& r3,
                                      uint32_t addr) {
    asm volatile("ldmatrix.sync.aligned.m8n8.x4.shared.b16 {%0,%1,%2,%3}, [%4];"
                 : "=r"(r0), "=r"(r1), "=r"(r2), "=r"(r3) : "r"(addr));
}
__device__ __forceinline__ void ldsm4t(uint32_t& r0, uint32_t& r1, uint32_t& r2, uint32_t& r3,
                                       uint32_t addr) {
    asm volatile("ldmatrix.sync.aligned.m8n8.x4.trans.shared.b16 {%0,%1,%2,%3}, [%4];"
                 : "=r"(r0), "=r"(r1), "=r"(r2), "=r"(r3) : "r"(addr));
}
__device__ __forceinline__ void mma_bf16(float c[4], uint32_t a0, uint32_t a1, uint32_t a2,
                                         uint32_t a3, uint32_t b0, uint32_t b1) {
    asm volatile(
        "mma.sync.aligned.m16n8k16.row.col.f32.bf16.bf16.f32 "
        "{%0,%1,%2,%3}, {%4,%5,%6,%7}, {%8,%9}, {%0,%1,%2,%3};"
        : "+f"(c[0]), "+f"(c[1]), "+f"(c[2]), "+f"(c[3])
        : "r"(a0), "r"(a1), "r"(a2), "r"(a3), "r"(b0), "r"(b1));
}
__device__ __forceinline__ void mma_fp16(float c[4], uint32_t a0, uint32_t a1, uint32_t a2,
                                         uint32_t a3, uint32_t b0, uint32_t b1) {
    asm volatile(
        "mma.sync.aligned.m16n8k16.row.col.f32.f16.f16.f32 "
        "{%0,%1,%2,%3}, {%4,%5,%6,%7}, {%8,%9}, {%0,%1,%2,%3};"
        : "+f"(c[0]), "+f"(c[1]), "+f"(c[2]), "+f"(c[3])
        : "r"(a0), "r"(a1), "r"(a2), "r"(a3), "r"(b0), "r"(b1));
}

// ---------------- K1: Gram via HMMA (split-bf16 exact), direct-fragment epilogue ----
// grid 512 (b*64 + y), 256 threads. T[token 64][hi|lo] bf16, stride 136.
// G = T.T^T + T.Tswap^T (exact product of x.x^T).
#define GTS 136
__global__ __launch_bounds__(256) void gram_kernel(const float* __restrict__ x) {
    __shared__ __align__(16) __nv_bfloat16 T[64 * GTS];
    __shared__ float m1w[8][64];

    int b = blockIdx.x >> 6, y = blockIdx.x & 63;
    int tid = threadIdx.x, w = tid >> 5, l = tid & 31;
    uint32_t t_b = smem_u32(T);

    m1w[w][l] = 0.f; m1w[w][l + 32] = 0.f;

    const float* xb = x + b * 262144;
    #pragma unroll
    for (int it = 0; it < 4; ++it) {
        int f4 = it * 256 + tid;            // 0..1023
        int j = f4 >> 4, x4 = f4 & 15;
        float4 v = *(const float4*)(xb + ((j >> 3) * 64 + y) * 512 + (j & 7) * 64 + x4 * 4);
        __nv_bfloat162 h01 = __float22bfloat162_rn(make_float2(v.x, v.y));
        __nv_bfloat162 h23 = __float22bfloat162_rn(make_float2(v.z, v.w));
        float2 f01 = __bfloat1622float2(h01);
        float2 f23 = __bfloat1622float2(h23);
        __nv_bfloat162 l01 = __float22bfloat162_rn(make_float2(v.x - f01.x, v.y - f01.y));
        __nv_bfloat162 l23 = __float22bfloat162_rn(make_float2(v.z - f23.x, v.w - f23.y));
        *(uint2*)&T[j * GTS + x4 * 4]      = make_uint2(*(uint32_t*)&h01, *(uint32_t*)&h23);
        *(uint2*)&T[j * GTS + 64 + x4 * 4] = make_uint2(*(uint32_t*)&l01, *(uint32_t*)&l23);
        float s4 = (v.x + v.y) + (v.z + v.w);
        s4 += __shfl_xor_sync(0xffffffffu, s4, 1);
        s4 += __shfl_xor_sync(0xffffffffu, s4, 2);
        s4 += __shfl_xor_sync(0xffffffffu, s4, 4);
        s4 += __shfl_xor_sync(0xffffffffu, s4, 8);
        if ((l & 15) == 0) m1w[w][j] += s4;
    }
    __syncthreads();

    if (tid < 64) {
        float s = 0.f;
        #pragma unroll
        for (int ww = 0; ww < 8; ++ww) s += m1w[ww][tid];
        g_m1part[(b * 64 + y) * 64 + tid] = s;
    }

    int rw = w & 3, nh = w >> 2;
    int r0 = 16 * rw, n0 = 32 * nh;
    float c[4][4];
    #pragma unroll
    for (int q = 0; q < 4; ++q)
        #pragma unroll
        for (int e = 0; e < 4; ++e) c[q][e] = 0.f;

    int arow = r0 + (l & 15), ak = (l >> 4) << 3;
    int brow = ((l >> 4) << 3) + (l & 7), bk = ((l >> 3) & 1) << 3;

    #pragma unroll
    for (int kk = 0; kk < 128; kk += 16) {
        uint32_t a0, a1, a2, a3;
        ldsm4(a0, a1, a2, a3, t_b + (arow * GTS + kk + ak) * 2);
        int kc = kk ^ 64;                   // swapped-half k for cross terms
        #pragma unroll
        for (int t = 0; t < 2; ++t) {
            int row = n0 + 16 * t + brow;
            uint32_t b0, b1, b2, b3;
            ldsm4(b0, b1, b2, b3, t_b + (row * GTS + kk + bk) * 2);
            mma_bf16(c[2 * t],     a0, a1, a2, a3, b0, b1);
            mma_bf16(c[2 * t + 1], a0, a1, a2, a3, b2, b3);
            ldsm4(b0, b1, b2, b3, t_b + (row * GTS + kc + bk) * 2);
            mma_bf16(c[2 * t],     a0, a1, a2, a3, b0, b1);
            mma_bf16(c[2 * t + 1], a0, a1, a2, a3, b2, b3);
        }
    }

    float* gp = &g_Gpart[(b * 64 + y) * 4096];
    int er = r0 + (l >> 2), ec = 2 * (l & 3);
    #pragma unroll
    for (int q = 0; q < 4; ++q) {
        int col = n0 + 16 * (q >> 1) + 8 * (q & 1) + ec;
        *(float2*)&gp[er * 64 + col]       = make_float2(c[q][0], c[q][1]);
        *(float2*)&gp[(er + 8) * 64 + col] = make_float2(c[q][2], c[q][3]);
    }
}

// ---------------- K2: consts + reduce + softmax -> fp16 M, ONE G-row per block ----
// grid (8 batches, 64 rows), 256 threads.
__global__ __launch_bounds__(256) void attn_kernel(
        const float* __restrict__ w1, const float* __restrict__ b1,
        const float* __restrict__ wqkv, const float* __restrict__ wproj,
        const float* __restrict__ bproj, const float* __restrict__ w2,
        const float* __restrict__ b2) {
    int b = blockIdx.x, i = blockIdx.y, tid = threadIdx.x;
    __shared__ float A[96], B0[96], tC[32];
    __shared__ float sal[4], sbe[4], sga[4], sde[4], swh[4];
    __shared__ float red[4][64], red2[4][64];
    __shared__ float Gs[64], m1s[64];

    if (tid < 96) {
        float a = 0.f, bb = 0.f;
        #pragma unroll
        for (int c = 0; c < 32; ++c) {
            float wv = wqkv[tid * 32 + c];
            a += wv * w1[c];
            bb += wv * b1[c];
        }
        A[tid] = a; B0[tid] = bb;
    }
    if (tid >= 128 && tid < 160) {
        int c = tid - 128;
        float s = 0.f;
        #pragma unroll
        for (int o = 0; o < 32; ++o) s += w2[o] * wproj[o * 32 + c];
        tC[c] = s;
    }

    {
        int j = tid & 63, q = tid >> 6;
        const float* gp = &g_Gpart[b * 262144 + i * 64 + j];
        float s = 0.f;
        #pragma unroll
        for (int c = 0; c < 16; ++c) s += gp[(q * 16 + c) * 4096];
        red[q][j] = s;
        const float* mp = &g_m1part[b * 4096 + j];
        float s2 = 0.f;
        #pragma unroll
        for (int c = 0; c < 16; ++c) s2 += mp[(q * 16 + c) * 64];
        red2[q][j] = s2;
    }
    __syncthreads();

    if (tid >= 128 && tid < 132) {
        int h = tid - 128;
        float al = 0.f, be = 0.f, ga = 0.f, de = 0.f, wh = 0.f;
        #pragma unroll
        for (int dd = 0; dd < 8; ++dd) {
            int c = h * 8 + dd;
            float aq = A[c], ak = A[32 + c], bq = B0[c], bk = B0[32 + c];
            al += aq * ak; be += aq * bk; ga += bq * ak; de += bq * bk;
            wh += tC[c] * A[64 + c];
        }
        sal[h] = al; sbe[h] = be; sga[h] = ga; sde[h] = de; swh[h] = wh;
    }
    if (tid == 132) {
        float c = b2[0];
        #pragma unroll
        for (int o = 0; o < 32; ++o) c += w2[o] * bproj[o];
        #pragma unroll
        for (int cc = 0; cc < 32; ++cc) c += tC[cc] * B0[64 + cc];
        g_cst[0] = c;
    }
    if (tid < 64) {
        Gs[tid]  = (red[0][tid] + red[1][tid]) + (red[2][tid] + red[3][tid]);
        m1s[tid] = (red2[0][tid] + red2[1][tid]) + (red2[2][tid] + red2[3][tid]);
    }
    __syncthreads();

    if (tid < 32) {
        int l = tid;
        const float scale = 1.0f / (4096.0f * 2.8284271247461903f);
        float g0 = Gs[l], g1 = Gs[l + 32];
        float m1i = m1s[i], m1l = m1s[l], m1l2 = m1s[l + 32];
        float acc0 = 0.f, acc1 = 0.f;
        #pragma unroll
        for (int h = 0; h < 4; ++h) {
            float al = sal[h] * scale, be = sbe[h] * scale;
            float ga = sga[h] * scale, de = sde[h] * scale * 4096.f;
            float whh = swh[h];
            float base = be * m1i + de;
            float s0 = al * g0 + ga * m1l  + base;
            float s1 = al * g1 + ga * m1l2 + base;
            float mx = fmaxf(s0, s1);
            #pragma unroll
            for (int off = 16; off > 0; off >>= 1)
                mx = fmaxf(mx, __shfl_xor_sync(0xffffffffu, mx, off));
            float e0 = __expf(s0 - mx), e1 = __expf(s1 - mx);
            float sm = e0 + e1;
            #pragma unroll
            for (int off = 16; off > 0; off >>= 1)
                sm += __shfl_xor_sync(0xffffffffu, sm, off);
            float f = whh / sm;
            acc0 += e0 * f; acc1 += e1 * f;
        }
        __half* mo = &g_Mh[b * 4096 + i * 64];
        mo[l]      = __float2half_rn(acc0);
        mo[l + 32] = __float2half_rn(acc1);
    }
}

// ---------------- K3: out = M @ X + const via single-pass fp16 HMMA (trans-B) ----
// grid 512 (b*64+y), 256 threads. Asm = M fp16 64x64 (stride 72);
// Bsm = X fp16 [j][x 64] (stride 72) -> ldmatrix.trans. 4 k16 iterations.
#define OTS 72
__global__ __launch_bounds__(256) void out_kernel(const float* __restrict__ x,
                                                  float* __restrict__ out) {
    __shared__ __align__(16) __half Asm[64 * OTS];
    __shared__ __align__(16) __half Bsm[64 * OTS];

    int b = blockIdx.x >> 6, y = blockIdx.x & 63;
    int tid = threadIdx.x, w = tid >> 5, l = tid & 31;
    uint32_t a_b = smem_u32(Asm), b_b = smem_u32(Bsm);

    // load M (64x64 fp16) with padded stride
    const uint4* mg = (const uint4*)&g_Mh[b * 4096];
    #pragma unroll
    for (int it = 0; it < 2; ++it) {
        int u = it * 256 + tid;             // 0..511, 8 halves each
        int row = u >> 3, c8 = (u & 7) * 8;
        *(uint4*)&Asm[row * OTS + c8] = mg[u];
    }

    // convert X row y -> Bsm[j][x] fp16
    const float* xb = x + b * 262144;
    #pragma unroll
    for (int it = 0; it < 4; ++it) {
        int f4 = it * 256 + tid;
        int j = f4 >> 4, x4 = f4 & 15;
        float4 v = *(const float4*)(xb + ((j >> 3) * 64 + y) * 512 + (j & 7) * 64 + x4 * 4);
        __half2 h01 = __float22half2_rn(make_float2(v.x, v.y));
        __half2 h23 = __float22half2_rn(make_float2(v.z, v.w));
        *(uint2*)&Bsm[j * OTS + x4 * 4] = make_uint2(*(uint32_t*)&h01, *(uint32_t*)&h23);
    }
    __syncthreads();

    int rw = w & 3, nh = w >> 2;
    int r0 = 16 * rw;
    float c[4][4];
    #pragma unroll
    for (int t = 0; t < 4; ++t)
        #pragma unroll
        for (int q = 0; q < 4; ++q) c[t][q] = 0.f;

    int arow = r0 + (l & 15), ak = (l >> 4) << 3;
    int btrow = l & 15, btcol = (l >> 4) << 3;   // trans: rows = k (j), cols = n (x)

    #pragma unroll
    for (int kk = 0; kk < 64; kk += 16) {
        uint32_t a0, a1, a2, a3;
        ldsm4(a0, a1, a2, a3, a_b + (arow * OTS + kk + ak) * 2);
        #pragma unroll
        for (int t = 0; t < 2; ++t) {
            int n0 = nh * 32 + 16 * t;
            uint32_t b0, b1, b2, b3;
            ldsm4t(b0, b1, b2, b3, b_b + ((kk + btrow) * OTS + n0 + btcol) * 2);
            mma_fp16(c[2 * t],     a0, a1, a2, a3, b0, b1);
            mma_fp16(c[2 * t + 1], a0, a1, a2, a3, b2, b3);
        }
    }

    float cst = g_cst[0];
    float* ob = out + b * 262144;
    int er = r0 + (l >> 2), ec = 2 * (l & 3);
    #pragma unroll
    for (int t = 0; t < 4; ++t) {
        int col = nh * 32 + 8 * t + ec;
        int s0 = er, s1 = er + 8;
        *(float2*)&ob[((s0 >> 3) * 64 + y) * 512 + (s0 & 7) * 64 + col] =
            make_float2(c[t][0] + cst, c[t][1] + cst);
        *(float2*)&ob[((s1 >> 3) * 64 + y) * 512 + (s1 & 7) * 64 + col] =
            make_float2(c[t][2] + cst, c[t][3] + cst);
    }
}

extern "C" void kernel_launch(void* const* d_in, const int* in_sizes, int n_in,
                              void* d_out, int out_size) {
    const float* x     = (const float*)d_in[0];
    const float* w1    = (const float*)d_in[3];
    const float* b1    = (const float*)d_in[4];
    const float* wqkv  = (const float*)d_in[5];
    const float* wproj = (const float*)d_in[6];
    const float* bproj = (const float*)d_in[7];
    const float* w2    = (const float*)d_in[8];
    const float* b2    = (const float*)d_in[9];
    float* out = (float*)d_out;

    gram_kernel<<<512, 256>>>(x);
    attn_kernel<<<dim3(8, 64), 256>>>(w1, b1, wqkv, wproj, bproj, w2, b2);
    out_kernel<<<512, 256>>>(x, out);
}

// round 17
// speedup vs baseline: 2.1097x; 1.0764x over previous
#include <cuda_runtime.h>
#include <cuda_bf16.h>
#include <cuda_fp16.h>
#include <cstdint>

// ---------------- scratch ----------------
__device__ float g_Gpart[8 * 64 * 64 * 64];   // split-K gram partials (8 MB)
__device__ float g_m1part[8 * 64 * 64];       // token-sum partials
__device__ __half g_Mh[8 * 64 * 64];          // mixing matrix fp16 [b][s][j]
__device__ float g_cst[1];

__device__ __forceinline__ uint32_t smem_u32(const void* p) {
    uint32_t a;
    asm("{ .reg .u64 t; cvta.to.shared.u64 t, %1; cvt.u32.u64 %0, t; }" : "=r"(a) : "l"(p));
    return a;
}
__device__ __forceinline__ void ldsm4(uint32_t& r0, uint32_t& r1, uint32_t& r2, uint32_t& r3,
                                      uint32_t addr) {
    asm volatile("ldmatrix.sync.aligned.m8n8.x4.shared.b16 {%0,%1,%2,%3}, [%4];"
                 : "=r"(r0), "=r"(r1), "=r"(r2), "=r"(r3) : "r"(addr));
}
__device__ __forceinline__ void ldsm4t(uint32_t& r0, uint32_t& r1, uint32_t& r2, uint32_t& r3,
                                       uint32_t addr) {
    asm volatile("ldmatrix.sync.aligned.m8n8.x4.trans.shared.b16 {%0,%1,%2,%3}, [%4];"
                 : "=r"(r0), "=r"(r1), "=r"(r2), "=r"(r3) : "r"(addr));
}
__device__ __forceinline__ void mma_fp16(float c[4], uint32_t a0, uint32_t a1, uint32_t a2,
                                         uint32_t a3, uint32_t b0, uint32_t b1) {
    asm volatile(
        "mma.sync.aligned.m16n8k16.row.col.f32.f16.f16.f32 "
        "{%0,%1,%2,%3}, {%4,%5,%6,%7}, {%8,%9}, {%0,%1,%2,%3};"
        : "+f"(c[0]), "+f"(c[1]), "+f"(c[2]), "+f"(c[3])
        : "r"(a0), "r"(a1), "r"(a2), "r"(a3), "r"(b0), "r"(b1));
}

#define TS 72   // fp16 tile row stride (144B): ldsm/ldsmt conflict-free

// ---------------- K1: Gram via single-pass fp16 HMMA, direct-fragment epilogue ----
// grid 512 (b*64 + y), 256 threads (8 warps). T[token 64][k 64] fp16, stride 72.
// G ~= T.T^T (fp16 rounding error in G perturbs softmax scores by ~1e-7 rel).
__global__ __launch_bounds__(256) void gram_kernel(const float* __restrict__ x) {
    __shared__ __align__(16) __half T[64 * TS];
    __shared__ float m1w[8][64];

    int b = blockIdx.x >> 6, y = blockIdx.x & 63;
    int tid = threadIdx.x, w = tid >> 5, l = tid & 31;
    uint32_t t_b = smem_u32(T);

    m1w[w][l] = 0.f; m1w[w][l + 32] = 0.f;

    const float* xb = x + b * 262144;
    #pragma unroll
    for (int it = 0; it < 4; ++it) {
        int f4 = it * 256 + tid;            // 0..1023
        int j = f4 >> 4, x4 = f4 & 15;
        float4 v = *(const float4*)(xb + ((j >> 3) * 64 + y) * 512 + (j & 7) * 64 + x4 * 4);
        __half2 h01 = __float22half2_rn(make_float2(v.x, v.y));
        __half2 h23 = __float22half2_rn(make_float2(v.z, v.w));
        *(uint2*)&T[j * TS + x4 * 4] = make_uint2(*(uint32_t*)&h01, *(uint32_t*)&h23);
        float s4 = (v.x + v.y) + (v.z + v.w);
        s4 += __shfl_xor_sync(0xffffffffu, s4, 1);
        s4 += __shfl_xor_sync(0xffffffffu, s4, 2);
        s4 += __shfl_xor_sync(0xffffffffu, s4, 4);
        s4 += __shfl_xor_sync(0xffffffffu, s4, 8);
        if ((l & 15) == 0) m1w[w][j] += s4;
    }
    __syncthreads();

    if (tid < 64) {
        float s = 0.f;
        #pragma unroll
        for (int ww = 0; ww < 8; ++ww) s += m1w[ww][tid];
        g_m1part[(b * 64 + y) * 64 + tid] = s;
    }

    int rw = w & 3, nh = w >> 2;
    int r0 = 16 * rw, n0 = 32 * nh;
    float c[4][4];
    #pragma unroll
    for (int q = 0; q < 4; ++q)
        #pragma unroll
        for (int e = 0; e < 4; ++e) c[q][e] = 0.f;

    int arow = r0 + (l & 15), ak = (l >> 4) << 3;
    int brow = ((l >> 4) << 3) + (l & 7), bk = ((l >> 3) & 1) << 3;

    #pragma unroll
    for (int kk = 0; kk < 64; kk += 16) {
        uint32_t a0, a1, a2, a3;
        ldsm4(a0, a1, a2, a3, t_b + (arow * TS + kk + ak) * 2);
        #pragma unroll
        for (int t = 0; t < 2; ++t) {
            int row = n0 + 16 * t + brow;
            uint32_t b0, b1, b2, b3;
            ldsm4(b0, b1, b2, b3, t_b + (row * TS + kk + bk) * 2);
            mma_fp16(c[2 * t],     a0, a1, a2, a3, b0, b1);
            mma_fp16(c[2 * t + 1], a0, a1, a2, a3, b2, b3);
        }
    }

    float* gp = &g_Gpart[(b * 64 + y) * 4096];
    int er = r0 + (l >> 2), ec = 2 * (l & 3);
    #pragma unroll
    for (int q = 0; q < 4; ++q) {
        int col = n0 + 16 * (q >> 1) + 8 * (q & 1) + ec;
        *(float2*)&gp[er * 64 + col]       = make_float2(c[q][0], c[q][1]);
        *(float2*)&gp[(er + 8) * 64 + col] = make_float2(c[q][2], c[q][3]);
    }
}

// ---------------- K2: consts + reduce + softmax -> fp16 M, ONE G-row per block ----
// grid (8 batches, 64 rows), 256 threads.
__global__ __launch_bounds__(256) void attn_kernel(
        const float* __restrict__ w1, const float* __restrict__ b1,
        const float* __restrict__ wqkv, const float* __restrict__ wproj,
        const float* __restrict__ bproj, const float* __restrict__ w2,
        const float* __restrict__ b2) {
    int b = blockIdx.x, i = blockIdx.y, tid = threadIdx.x;
    __shared__ float A[96], B0[96], tC[32];
    __shared__ float sal[4], sbe[4], sga[4], sde[4], swh[4];
    __shared__ float red[4][64], red2[4][64];
    __shared__ float Gs[64], m1s[64];

    if (tid < 96) {
        float a = 0.f, bb = 0.f;
        #pragma unroll
        for (int c = 0; c < 32; ++c) {
            float wv = wqkv[tid * 32 + c];
            a += wv * w1[c];
            bb += wv * b1[c];
        }
        A[tid] = a; B0[tid] = bb;
    }
    if (tid >= 128 && tid < 160) {
        int c = tid - 128;
        float s = 0.f;
        #pragma unroll
        for (int o = 0; o < 32; ++o) s += w2[o] * wproj[o * 32 + c];
        tC[c] = s;
    }

    {
        int j = tid & 63, q = tid >> 6;
        const float* gp = &g_Gpart[b * 262144 + i * 64 + j];
        float s = 0.f;
        #pragma unroll
        for (int c = 0; c < 16; ++c) s += gp[(q * 16 + c) * 4096];
        red[q][j] = s;
        const float* mp = &g_m1part[b * 4096 + j];
        float s2 = 0.f;
        #pragma unroll
        for (int c = 0; c < 16; ++c) s2 += mp[(q * 16 + c) * 64];
        red2[q][j] = s2;
    }
    __syncthreads();

    if (tid >= 128 && tid < 132) {
        int h = tid - 128;
        float al = 0.f, be = 0.f, ga = 0.f, de = 0.f, wh = 0.f;
        #pragma unroll
        for (int dd = 0; dd < 8; ++dd) {
            int c = h * 8 + dd;
            float aq = A[c], ak = A[32 + c], bq = B0[c], bk = B0[32 + c];
            al += aq * ak; be += aq * bk; ga += bq * ak; de += bq * bk;
            wh += tC[c] * A[64 + c];
        }
        sal[h] = al; sbe[h] = be; sga[h] = ga; sde[h] = de; swh[h] = wh;
    }
    if (tid == 132) {
        float c = b2[0];
        #pragma unroll
        for (int o = 0; o < 32; ++o) c += w2[o] * bproj[o];
        #pragma unroll
        for (int cc = 0; cc < 32; ++cc) c += tC[cc] * B0[64 + cc];
        g_cst[0] = c;
    }
    if (tid < 64) {
        Gs[tid]  = (red[0][tid] + red[1][tid]) + (red[2][tid] + red[3][tid]);
        m1s[tid] = (red2[0][tid] + red2[1][tid]) + (red2[2][tid] + red2[3][tid]);
    }
    __syncthreads();

    if (tid < 32) {
        int l = tid;
        const float scale = 1.0f / (4096.0f * 2.8284271247461903f);
        float g0 = Gs[l], g1 = Gs[l + 32];
        float m1i = m1s[i], m1l = m1s[l], m1l2 = m1s[l + 32];
        float acc0 = 0.f, acc1 = 0.f;
        #pragma unroll
        for (int h = 0; h < 4; ++h) {
            float al = sal[h] * scale, be = sbe[h] * scale;
            float ga = sga[h] * scale, de = sde[h] * scale * 4096.f;
            float whh = swh[h];
            float base = be * m1i + de;
            float s0 = al * g0 + ga * m1l  + base;
            float s1 = al * g1 + ga * m1l2 + base;
            float mx = fmaxf(s0, s1);
            #pragma unroll
            for (int off = 16; off > 0; off >>= 1)
                mx = fmaxf(mx, __shfl_xor_sync(0xffffffffu, mx, off));
            float e0 = __expf(s0 - mx), e1 = __expf(s1 - mx);
            float sm = e0 + e1;
            #pragma unroll
            for (int off = 16; off > 0; off >>= 1)
                sm += __shfl_xor_sync(0xffffffffu, sm, off);
            float f = whh / sm;
            acc0 += e0 * f; acc1 += e1 * f;
        }
        __half* mo = &g_Mh[b * 4096 + i * 64];
        mo[l]      = __float2half_rn(acc0);
        mo[l + 32] = __float2half_rn(acc1);
    }
}

// ---------------- K3: out = M @ X + const via single-pass fp16 HMMA (trans-B) ----
// grid 512 (b*64+y), 256 threads. Asm = M fp16 64x64 (stride 72);
// Bsm = X fp16 [j][x 64] (stride 72) -> ldmatrix.trans. 4 k16 iterations.
__global__ __launch_bounds__(256) void out_kernel(const float* __restrict__ x,
                                                  float* __restrict__ out) {
    __shared__ __align__(16) __half Asm[64 * TS];
    __shared__ __align__(16) __half Bsm[64 * TS];

    int b = blockIdx.x >> 6, y = blockIdx.x & 63;
    int tid = threadIdx.x, w = tid >> 5, l = tid & 31;
    uint32_t a_b = smem_u32(Asm), b_b = smem_u32(Bsm);

    // load M (64x64 fp16) with padded stride
    const uint4* mg = (const uint4*)&g_Mh[b * 4096];
    #pragma unroll
    for (int it = 0; it < 2; ++it) {
        int u = it * 256 + tid;             // 0..511, 8 halves each
        int row = u >> 3, c8 = (u & 7) * 8;
        *(uint4*)&Asm[row * TS + c8] = mg[u];
    }

    // convert X row y -> Bsm[j][x] fp16
    const float* xb = x + b * 262144;
    #pragma unroll
    for (int it = 0; it < 4; ++it) {
        int f4 = it * 256 + tid;
        int j = f4 >> 4, x4 = f4 & 15;
        float4 v = *(const float4*)(xb + ((j >> 3) * 64 + y) * 512 + (j & 7) * 64 + x4 * 4);
        __half2 h01 = __float22half2_rn(make_float2(v.x, v.y));
        __half2 h23 = __float22half2_rn(make_float2(v.z, v.w));
        *(uint2*)&Bsm[j * TS + x4 * 4] = make_uint2(*(uint32_t*)&h01, *(uint32_t*)&h23);
    }
    __syncthreads();

    int rw = w & 3, nh = w >> 2;
    int r0 = 16 * rw;
    float c[4][4];
    #pragma unroll
    for (int t = 0; t < 4; ++t)
        #pragma unroll
        for (int q = 0; q < 4; ++q) c[t][q] = 0.f;

    int arow = r0 + (l & 15), ak = (l >> 4) << 3;
    int btrow = l & 15, btcol = (l >> 4) << 3;   // trans: rows = k (j), cols = n (x)

    #pragma unroll
    for (int kk = 0; kk < 64; kk += 16) {
        uint32_t a0, a1, a2, a3;
        ldsm4(a0, a1, a2, a3, a_b + (arow * TS + kk + ak) * 2);
        #pragma unroll
        for (int t = 0; t < 2; ++t) {
            int n0 = nh * 32 + 16 * t;
            uint32_t b0, b1, b2, b3;
            ldsm4t(b0, b1, b2, b3, b_b + ((kk + btrow) * TS + n0 + btcol) * 2);
            mma_fp16(c[2 * t],     a0, a1, a2, a3, b0, b1);
            mma_fp16(c[2 * t + 1], a0, a1, a2, a3, b2, b3);
        }
    }

    float cst = g_cst[0];
    float* ob = out + b * 262144;
    int er = r0 + (l >> 2), ec = 2 * (l & 3);
    #pragma unroll
    for (int t = 0; t < 4; ++t) {
        int col = nh * 32 + 8 * t + ec;
        int s0 = er, s1 = er + 8;
        *(float2*)&ob[((s0 >> 3) * 64 + y) * 512 + (s0 & 7) * 64 + col] =
            make_float2(c[t][0] + cst, c[t][1] + cst);
        *(float2*)&ob[((s1 >> 3) * 64 + y) * 512 + (s1 & 7) * 64 + col] =
            make_float2(c[t][2] + cst, c[t][3] + cst);
    }
}

extern "C" void kernel_launch(void* const* d_in, const int* in_sizes, int n_in,
                              void* d_out, int out_size) {
    const float* x     = (const float*)d_in[0];
    const float* w1    = (const float*)d_in[3];
    const float* b1    = (const float*)d_in[4];
    const float* wqkv  = (const float*)d_in[5];
    const float* wproj = (const float*)d_in[6];
    const float* bproj = (const float*)d_in[7];
    const float* w2    = (const float*)d_in[8];
    const float* b2    = (const float*)d_in[9];
    float* out = (float*)d_out;

    gram_kernel<<<512, 256>>>(x);
    attn_kernel<<<dim3(8, 64), 256>>>(w1, b1, wqkv, wproj, bproj, w2, b2);
    out_kernel<<<512, 256>>>(x, out);
}